// round 11
// baseline (speedup 1.0000x reference)
#include <cuda_runtime.h>
#include <math.h>
#include <stdint.h>

#define NQ    20
#define NL    4
#define BATCH 16
#define DIM   (1 << NQ)

#define CB      8                      // batches per chunk
#define NCHUNK  (BATCH / CB)

__device__ float  g_bufA[CB * DIM];
__device__ float  g_bufB[CB * DIM];
__device__ float2 g_rf[NL * NQ];   // .x = ratio (|r|<=1), .y = form (0 or 1)
__device__ float  g_absC;

// ---------------------------------------------------------------------------
__global__ void sincos_kernel(const float* __restrict__ theta) {
    __shared__ float sc[NL * NQ];
    int i = threadIdx.x;
    if (i < NL * NQ) {
        float t = 0.5f * theta[i];
        float c = cosf(t), s = sinf(t);
        bool form = fabsf(s) > fabsf(c);
        g_rf[i] = make_float2(form ? (c / s) : (s / c), form ? 1.0f : 0.0f);
        sc[i] = form ? s : c;
    }
    __syncthreads();
    if (i == 0) {
        float p = 1.0f;
        for (int k = 0; k < NL * NQ; k++) p *= sc[k];
        g_absC = fabsf(p);
    }
}

// ---------------------------------------------------------------------------
union F2U { float2 f; unsigned long long u; };
__device__ __forceinline__ float2 ffma2(float2 a, float2 b, float2 c) {
    F2U ua, ub, uc, ud;
    ua.f = a; ub.f = b; uc.f = c;
    asm("fma.rn.f32x2 %0, %1, %2, %3;" : "=l"(ud.u) : "l"(ua.u), "l"(ub.u), "l"(uc.u));
    return ud.f;
}
__device__ __forceinline__ float2 neg2(float2 v) {
    F2U x; x.f = v; x.u ^= 0x8000000080000000ULL; return x.f;
}
__device__ __forceinline__ float xsign(float v, uint32_t sg) {
    return __uint_as_float(__float_as_uint(v) ^ sg);
}

// Packed butterfly stage over 8 float2.
__device__ __forceinline__ void pstage8(float2* v, int m, float2 rf) {
    float2 r2  = make_float2(rf.x, rf.x);
    float2 nr2 = make_float2(-rf.x, -rf.x);
    if (rf.y == 0.0f) {
#pragma unroll
        for (int i = 0; i < 8; i++)
            if ((i & m) == 0) {
                float2 a = v[i], b = v[i | m];
                v[i]     = ffma2(nr2, b, a);
                v[i | m] = ffma2(r2,  a, b);
            }
    } else {
#pragma unroll
        for (int i = 0; i < 8; i++)
            if ((i & m) == 0) {
                float2 a = v[i], b = v[i | m];
                v[i]     = ffma2(r2, a, neg2(b));
                v[i | m] = ffma2(r2, b, a);
            }
    }
}

__device__ __forceinline__ void pshuf8(float2* v, int kbit, float2 rf, int lane) {
    int bit = (lane >> kbit) & 1;
    if (rf.y == 0.0f) {
        float rs = bit ? rf.x : -rf.x;
        float2 rs2 = make_float2(rs, rs);
#pragma unroll
        for (int i = 0; i < 8; i++) {
            float2 o;
            o.x = __shfl_xor_sync(0xffffffffu, v[i].x, 1 << kbit);
            o.y = __shfl_xor_sync(0xffffffffu, v[i].y, 1 << kbit);
            v[i] = ffma2(rs2, o, v[i]);
        }
    } else {
        float2 r2 = make_float2(rf.x, rf.x);
        unsigned long long sg = bit ? 0ULL : 0x8000000080000000ULL;
#pragma unroll
        for (int i = 0; i < 8; i++) {
            F2U o;
            o.f.x = __shfl_xor_sync(0xffffffffu, v[i].x, 1 << kbit);
            o.f.y = __shfl_xor_sync(0xffffffffu, v[i].y, 1 << kbit);
            o.u ^= sg;
            v[i] = ffma2(r2, v[i], o.f);
        }
    }
}

__device__ __forceinline__ float2 pair_stage(float2 v, float2 rf) {
    float2 o;
    if (rf.y == 0.0f) {
        o.x = fmaf(-rf.x, v.y, v.x);
        o.y = fmaf( rf.x, v.x, v.y);
    } else {
        o.x = fmaf(rf.x, v.x, -v.y);
        o.y = fmaf(rf.x, v.y,  v.x);
    }
    return o;
}

// ---------------------------------------------------------------------------
// Scalar stages for hh/ph
// ---------------------------------------------------------------------------
template <int N>
__device__ __forceinline__ void stage_fg(float* e, int m, float2 rf) {
    float r = rf.x;
    if (rf.y == 0.0f) {
#pragma unroll
        for (int j = 0; j < N; j++)
            if ((j & m) == 0) {
                float a = e[j], b = e[j | m];
                e[j]     = fmaf(-r, b, a);
                e[j | m] = fmaf( r, a, b);
            }
    } else {
#pragma unroll
        for (int j = 0; j < N; j++)
            if ((j & m) == 0) {
                float a = e[j], b = e[j | m];
                e[j]     = fmaf(r, a, -b);
                e[j | m] = fmaf(r, b,  a);
            }
    }
}

// plain lane stage over e[64]: partner = shfl_xor(e[u], xm), role fixed per thread
__device__ __forceinline__ void lane_stage64(float e[64], int xm, int role, float2 rf) {
    if (rf.y == 0.0f) {
        float rs = role ? rf.x : -rf.x;
#pragma unroll
        for (int u = 0; u < 64; u++) {
            float o = __shfl_xor_sync(0xffffffffu, e[u], xm);
            e[u] = fmaf(rs, o, e[u]);
        }
    } else {
        float r = rf.x;
        uint32_t sg = role ? 0u : 0x80000000u;
#pragma unroll
        for (int u = 0; u < 64; u++) {
            float o = __shfl_xor_sync(0xffffffffu, e[u], xm);
            e[u] = fmaf(r, e[u], xsign(o, sg));
        }
    }
}

// conj lane stage: role(u) = baseRole ^ parity(u); partner = shfl_xor(e[u], xm)
__device__ __forceinline__ void lane_conj64(float e[64], int xm, int baseRole, float2 rf) {
    if (rf.y == 0.0f) {
        float rs0 = baseRole ? rf.x : -rf.x;
#pragma unroll
        for (int u = 0; u < 64; u++) {
            float o = __shfl_xor_sync(0xffffffffu, e[u], xm);
            float rs = (__popc(u) & 1) ? -rs0 : rs0;
            e[u] = fmaf(rs, o, e[u]);
        }
    } else {
        float r = rf.x;
        uint32_t sg0 = baseRole ? 0u : 0x80000000u;
#pragma unroll
        for (int u = 0; u < 64; u++) {
            float o = __shfl_xor_sync(0xffffffffu, e[u], xm);
            uint32_t sg = (__popc(u) & 1) ? (sg0 ^ 0x80000000u) : sg0;
            e[u] = fmaf(r, e[u], xsign(o, sg));
        }
    }
}

// Conjugated H stage (P^-1 H P): couples u-pairs differing in bits {hb, hb-1}
template <int HB>
__device__ __forceinline__ void conj_stage(float e[64], float2 rf) {
    const int mask = 3 << (HB - 1);
    float r = rf.x;
    bool f1 = (rf.y != 0.0f);
    if (!f1) {
#pragma unroll
        for (int u = 0; u < 64; u++)
            if ((u & (1 << HB)) == 0) {
                int v = u ^ mask;
                int ra = __popc(u >> HB) & 1;
                int ia = ra ? v : u;
                int ib = ra ? u : v;
                float a = e[ia], b = e[ib];
                e[ia] = fmaf(-r, b, a);
                e[ib] = fmaf( r, a, b);
            }
    } else {
#pragma unroll
        for (int u = 0; u < 64; u++)
            if ((u & (1 << HB)) == 0) {
                int v = u ^ mask;
                int ra = __popc(u >> HB) & 1;
                int ia = ra ? v : u;
                int ib = ra ? u : v;
                float a = e[ia], b = e[ib];
                e[ia] = fmaf(r, a, -b);
                e[ib] = fmaf(r, b,  a);
            }
    }
}

// Conj stage coupling g{14,13} = (u bit0, lane bit0): partner shfl_xor(e[u^1],1)
__device__ __forceinline__ void conj_r5_stage(float e[64], float2 rf) {
    float r = rf.x;
    bool f1 = (rf.y != 0.0f);
#pragma unroll
    for (int u = 0; u < 64; u += 2) {
        float o0 = __shfl_xor_sync(0xffffffffu, e[u + 1], 1);
        float o1 = __shfl_xor_sync(0xffffffffu, e[u],     1);
        bool aFirst = ((__popc(u) & 1) == 0);
        if (!f1) {
            if (aFirst) {
                e[u]     = fmaf(-r, o0, e[u]);
                e[u + 1] = fmaf( r, o1, e[u + 1]);
            } else {
                e[u]     = fmaf( r, o0, e[u]);
                e[u + 1] = fmaf(-r, o1, e[u + 1]);
            }
        } else {
            if (aFirst) {
                e[u]     = fmaf(r, e[u],     -o0);
                e[u + 1] = fmaf(r, e[u + 1],  o1);
            } else {
                e[u]     = fmaf(r, e[u],      o0);
                e[u + 1] = fmaf(r, e[u + 1], -o1);
            }
        }
    }
}

__device__ __host__ __forceinline__ int gdec(int g) {
    int p = g;
    p ^= p >> 1; p ^= p >> 2; p ^= p >> 4; p ^= p >> 8; p ^= p >> 16;
    return p;
}
__device__ __forceinline__ int gd6(int u) {
    int p = u; p ^= p >> 1; p ^= p >> 2; p ^= p >> 4; return p & 63;
}

// ---------------------------------------------------------------------------
// HH kernel: (H1' incl q6) * P * (H0' incl q6), H' = qubits 0..6.
// Orbit g 19:12: u = g19:14 (64 regs), lane0 = g13, lane1 = g12.
// ---------------------------------------------------------------------------
__global__ void __launch_bounds__(256, 2) hh_kernel(const float* __restrict__ in,
                                                    float* __restrict__ out) {
    __shared__ float2 s0[7], s1[7];
    {
        int i = threadIdx.x;
        if (i < 7)       s0[i] = g_rf[i];
        else if (i < 14) s1[i - 7] = g_rf[NQ + (i - 7)];
    }
    __syncthreads();

    const int lane = threadIdx.x & 31;
    const int w    = threadIdx.x >> 5;     // 0..7
    const int l0 = lane & 1, l1 = (lane >> 1) & 1, lz = lane >> 2;

    for (int it = 0; it < 2; it++) {
        const int blk = blockIdx.x + it * 256;
        const int sub = blk & 63;
        const int pos = (sub << 6) | (w << 3) | lz;     // 12 bits
        const size_t bbase = (size_t)(blk >> 6) << 20;

        float e[64];
        const float* pin = in + bbase + ((l0 << 13) | (l1 << 12) | pos);
#pragma unroll
        for (int u = 0; u < 64; u++) e[u] = pin[u << 14];

        // plain layer-0: q0..5 on u bits, q6 on lane0 (g13)
        stage_fg<64>(e, 32, s0[0]);
        stage_fg<64>(e, 16, s0[1]);
        stage_fg<64>(e,  8, s0[2]);
        stage_fg<64>(e,  4, s0[3]);
        stage_fg<64>(e,  2, s0[4]);
        stage_fg<64>(e,  1, s0[5]);
        lane_stage64(e, 1, l0, s0[6]);

        // conj layer-1: q0..4 on u, q5 via (u0,lane0), q6 via (lane0,lane1)
        conj_stage<5>(e, s1[0]);
        conj_stage<4>(e, s1[1]);
        conj_stage<3>(e, s1[2]);
        conj_stage<2>(e, s1[3]);
        conj_stage<1>(e, s1[4]);
        conj_r5_stage(e, s1[5]);
        lane_conj64(e, 3, l0, s1[6]);

        // scatter with P
        const int A = (l0 ? 0x3FFF : 0) ^ (l1 ? 0x1FFF : 0) ^ gdec(pos);
        float* pa = out + bbase + A;
        float* pb = out + bbase + (A ^ 0x3FFF);
#pragma unroll
        for (int u = 0; u < 64; u++) {
            int hi = gd6(u) << 14;
            if (__popc(u) & 1) pb[hi] = e[u];
            else               pa[hi] = e[u];
        }
    }
}

// ---------------------------------------------------------------------------
// PH kernel: (H_l q0..6) * P. u = p19:14 (64 regs), lane0 = p13.
// ---------------------------------------------------------------------------
__global__ void __launch_bounds__(256, 2) ph_kernel(const float* __restrict__ in,
                                                    float* __restrict__ out,
                                                    int layer) {
    __shared__ float2 srf[7];
    if (threadIdx.x < 7) srf[threadIdx.x] = g_rf[layer * NQ + threadIdx.x];
    __syncthreads();

    const int lane = threadIdx.x & 31;
    const int w    = threadIdx.x >> 5;     // 0..7
    const int t0 = lane & 1, lp = lane >> 1;   // lp = pos bits 3:0

    for (int it = 0; it < 2; it++) {
        const int blk = blockIdx.x + it * 256;
        const int sub = blk & 63;
        const int pos = (sub << 7) | (w << 4) | lp;     // 13 bits
        const size_t bbase = (size_t)(blk >> 6) << 20;
        const int Gt = ((t0 << 13) ^ (t0 << 12)) ^ (pos ^ (pos >> 1));

        float e[64];
        const float* pin = in + bbase;
#pragma unroll
        for (int u = 0; u < 64; u++)
            e[u] = pin[((u << 14) ^ (u << 13)) ^ Gt];

        stage_fg<64>(e, 32, srf[0]);
        stage_fg<64>(e, 16, srf[1]);
        stage_fg<64>(e,  8, srf[2]);
        stage_fg<64>(e,  4, srf[3]);
        stage_fg<64>(e,  2, srf[4]);
        stage_fg<64>(e,  1, srf[5]);
        lane_stage64(e, 1, t0, srf[6]);

        float* pout = out + bbase + ((t0 << 13) | pos);
#pragma unroll
        for (int u = 0; u < 64; u++) pout[u << 14] = e[u];
    }
}

// ---------------------------------------------------------------------------
// L13 kernel: qubits 7..19 in 8192-float tiles. 512 thr x 8 float2, 32KB smem,
// 3 CTAs/SM. a = jj*512 + w*32 + t (f2 units); idx = 2a+p0.
//   pair=q19, t=q18..14, w=(q13,q12,q11,q10), jj=(q9,q8,q7)
// Phase1: pair + 5 shufs + jj stages. T1 (jj <-> w[2:0]) -> q13,12,11.
// T2 (one-bit remap) -> q10. FINAL folds P + abs*|C| into store.
// ---------------------------------------------------------------------------
template <bool FINAL>
__global__ void __launch_bounds__(512, 3) l13_kernel(const float* in,
                                                     float* out,
                                                     int layer) {
    __shared__ float2 sm2[4096];           // 32 KB
    __shared__ float2 srf[NQ];
    if (threadIdx.x < NQ) srf[threadIdx.x] = g_rf[layer * NQ + threadIdx.x];
    __syncthreads();

    const int t  = threadIdx.x & 31;
    const int w  = threadIdx.x >> 5;       // 0..15
    const int wh = w >> 1, wl = w & 1;

    for (int ti = blockIdx.x; ti < CB * 128; ti += gridDim.x) {
        const int batch = ti >> 7, tile = ti & 127;
        const size_t tb2 = ((size_t)batch << 19) + ((size_t)tile << 12);

        float2 v[8];
        const float2* p2 = ((const float2*)in) + tb2;
#pragma unroll
        for (int jj = 0; jj < 8; jj++) v[jj] = p2[jj * 512 + w * 32 + t];

#pragma unroll
        for (int jj = 0; jj < 8; jj++) v[jj] = pair_stage(v[jj], srf[19]);
        pshuf8(v, 0, srf[18], t);
        pshuf8(v, 1, srf[17], t);
        pshuf8(v, 2, srf[16], t);
        pshuf8(v, 3, srf[15], t);
        pshuf8(v, 4, srf[14], t);
        pstage8(v, 1, srf[9]);
        pstage8(v, 2, srf[8]);
        pstage8(v, 4, srf[7]);

        __syncthreads();                   // guard prev-iteration smem reads
#pragma unroll
        for (int jj = 0; jj < 8; jj++) sm2[jj * 512 + w * 32 + t] = v[jj];
        __syncthreads();
#pragma unroll
        for (int n = 0; n < 8; n++) v[n] = sm2[(w << 8) | (n << 5) | t];

        pstage8(v, 1, srf[13]);
        pstage8(v, 2, srf[12]);
        pstage8(v, 4, srf[11]);

        __syncthreads();
#pragma unroll
        for (int n = 0; n < 8; n++) sm2[(w << 8) | (n << 5) | t] = v[n];
        __syncthreads();
#pragma unroll
        for (int n = 0; n < 8; n++) v[n] = sm2[(wh << 9) | (n << 6) | (wl << 5) | t];

        pstage8(v, 4, srf[10]);            // q10 on n bit 2 (= a8)

        if (FINAL) {
            const float absC = g_absC;
            float* o = out + ((size_t)batch << 20);
            const int ath   = (wh << 9) | (wl << 5) | t;
            const int pbase = gdec((tile << 13) | (ath << 1));
#pragma unroll
            for (int n = 0; n < 8; n++) {
                int A = pbase ^ gdec(n << 7);      // folds to const per n
                float ax = fabsf(v[n].x) * absC;
                float ay = fabsf(v[n].y) * absC;
                float2 sv = (A & 1) ? make_float2(ay, ax) : make_float2(ax, ay);
                *((float2*)(o + (A & ~1))) = sv;
            }
        } else {
            float2* q2 = ((float2*)out) + tb2;
#pragma unroll
            for (int n = 0; n < 8; n++)
                q2[(wh << 9) | (n << 6) | (wl << 5) | t] = v[n];
        }
    }
}

// ---------------------------------------------------------------------------
extern "C" void kernel_launch(void* const* d_in, const int* in_sizes, int n_in,
                              void* d_out, int out_size) {
    const float* x     = (const float*)d_in[0];
    const float* theta = (const float*)d_in[1];
    float*       out   = (float*)d_out;

    float *bA = nullptr, *bB = nullptr;
    cudaGetSymbolAddress((void**)&bA, g_bufA);
    cudaGetSymbolAddress((void**)&bB, g_bufB);

    sincos_kernel<<<1, 128>>>(theta);

    const int GL = 444;   // 148 SMs x 3 CTAs: stride loop over 1024 tiles
    const int GH = 256;   // hh/ph: 512 units via it-loop x2

    for (int c = 0; c < NCHUNK; c++) {
        const float* xc = x   + ((size_t)c * CB << 20);
        float*       oc = out + ((size_t)c * CB << 20);

        l13_kernel<false><<<GL, 512>>>(xc, bA, 0);   // L0 (q7..19)
        hh_kernel<<<GH, 256>>>(bA, bB);              // H1'*P*H0' (q0..6)
        l13_kernel<false><<<GL, 512>>>(bB, bB, 1);   // L1 (in-place)
        ph_kernel<<<GH, 256>>>(bB, bA, 2);           // H2' * P
        l13_kernel<false><<<GL, 512>>>(bA, bA, 2);   // L2 (in-place)
        ph_kernel<<<GH, 256>>>(bA, bB, 3);           // H3' * P
        l13_kernel<true><<<GL, 512>>>(bB, oc, 3);    // P * L3, abs*|C|
    }
}

// round 12
// speedup vs baseline: 1.1380x; 1.1380x over previous
#include <cuda_runtime.h>
#include <math.h>
#include <stdint.h>

#define NQ    20
#define NL    4
#define BATCH 16
#define DIM   (1 << NQ)

#define CB      8                      // batches per chunk
#define NCHUNK  (BATCH / CB)

__device__ float  g_bufA[CB * DIM];
__device__ float  g_bufB[CB * DIM];
__device__ float2 g_rf[NL * NQ];   // .x = ratio (|r|<=1), .y = form (0 or 1)
__device__ float  g_absC;          // |product of per-gate scales|

// ---------------------------------------------------------------------------
// Fast-Givens precompute.
//   form0 (|c|>=|s|): M = c*[[1,-t],[t,1]], t=s/c
//   form1 (|s|> |c|): M = s*[[u,-1],[1,u]], u=c/s
// ---------------------------------------------------------------------------
__global__ void sincos_kernel(const float* __restrict__ theta) {
    __shared__ float sc[NL * NQ];
    int i = threadIdx.x;
    if (i < NL * NQ) {
        float t = 0.5f * theta[i];
        float c = cosf(t), s = sinf(t);
        bool form = fabsf(s) > fabsf(c);
        g_rf[i] = make_float2(form ? (c / s) : (s / c), form ? 1.0f : 0.0f);
        sc[i] = form ? s : c;
    }
    __syncthreads();
    if (i == 0) {
        float p = 1.0f;
        for (int k = 0; k < NL * NQ; k++) p *= sc[k];
        g_absC = fabsf(p);
    }
}

// ---------------------------------------------------------------------------
// Fast-Givens butterflies. 'a' = role-0 element:
//   form0: a' = a - r*b ; b' = b + r*a
//   form1: a' = r*a - b ; b' = r*b + a
// ---------------------------------------------------------------------------
template <int N>
__device__ __forceinline__ void stage_fg(float* e, int m, float2 rf) {
    float r = rf.x;
    if (rf.y == 0.0f) {
#pragma unroll
        for (int j = 0; j < N; j++)
            if ((j & m) == 0) {
                float a = e[j], b = e[j | m];
                e[j]     = fmaf(-r, b, a);
                e[j | m] = fmaf( r, a, b);
            }
    } else {
#pragma unroll
        for (int j = 0; j < N; j++)
            if ((j & m) == 0) {
                float a = e[j], b = e[j | m];
                e[j]     = fmaf(r, a, -b);
                e[j | m] = fmaf(r, b,  a);
            }
    }
}

__device__ __forceinline__ float xsign(float v, uint32_t sg) {
    return __uint_as_float(__float_as_uint(v) ^ sg);
}

__device__ __forceinline__ void stage_xlane_fg(float e[32], int kbit, float2 rf, int lane) {
    int bit = (lane >> kbit) & 1;
    if (rf.y == 0.0f) {
        float rs = bit ? rf.x : -rf.x;
#pragma unroll
        for (int j = 0; j < 32; j++) {
            float o = __shfl_xor_sync(0xffffffffu, e[j], 1 << kbit);
            e[j] = fmaf(rs, o, e[j]);
        }
    } else {
        float r = rf.x;
        uint32_t sg = bit ? 0u : 0x80000000u;
#pragma unroll
        for (int j = 0; j < 32; j++) {
            float o = __shfl_xor_sync(0xffffffffu, e[j], 1 << kbit);
            e[j] = fmaf(r, e[j], xsign(o, sg));
        }
    }
}

// Conjugated H stage (P^-1 H P): couples u-pairs differing in bits {hb, hb-1};
// role(u) = parity(u >> hb).
template <int HB>
__device__ __forceinline__ void conj_stage(float e[64], float2 rf) {
    const int mask = 3 << (HB - 1);
    float r = rf.x;
    bool f1 = (rf.y != 0.0f);
    if (!f1) {
#pragma unroll
        for (int u = 0; u < 64; u++)
            if ((u & (1 << HB)) == 0) {
                int v = u ^ mask;
                int ra = __popc(u >> HB) & 1;
                int ia = ra ? v : u;
                int ib = ra ? u : v;
                float a = e[ia], b = e[ib];
                e[ia] = fmaf(-r, b, a);
                e[ib] = fmaf( r, a, b);
            }
    } else {
#pragma unroll
        for (int u = 0; u < 64; u++)
            if ((u & (1 << HB)) == 0) {
                int v = u ^ mask;
                int ra = __popc(u >> HB) & 1;
                int ia = ra ? v : u;
                int ib = ra ? u : v;
                float a = e[ia], b = e[ib];
                e[ia] = fmaf(r, a, -b);
                e[ib] = fmaf(r, b,  a);
            }
    }
}

// Conjugated R5(layer1) stage inside hh: couples g bits {14,13} = (reg bit 0,
// lane bit 0). Partner of e[u] is shfl_xor(e[u^1], 1). Role 'a' = parity(u)==0.
__device__ __forceinline__ void conj_r5_stage(float e[64], float2 rf) {
    float r = rf.x;
    bool f1 = (rf.y != 0.0f);
#pragma unroll
    for (int u = 0; u < 64; u += 2) {
        float o0 = __shfl_xor_sync(0xffffffffu, e[u + 1], 1);
        float o1 = __shfl_xor_sync(0xffffffffu, e[u],     1);
        bool aFirst = ((__popc(u) & 1) == 0);
        if (!f1) {
            if (aFirst) {
                e[u]     = fmaf(-r, o0, e[u]);
                e[u + 1] = fmaf( r, o1, e[u + 1]);
            } else {
                e[u]     = fmaf( r, o0, e[u]);
                e[u + 1] = fmaf(-r, o1, e[u + 1]);
            }
        } else {
            if (aFirst) {
                e[u]     = fmaf(r, e[u],     -o0);
                e[u + 1] = fmaf(r, e[u + 1],  o1);
            } else {
                e[u]     = fmaf(r, e[u],      o0);
                e[u + 1] = fmaf(r, e[u + 1], -o1);
            }
        }
    }
}

// gray decode (p such that p ^ (p>>1) = g)
__device__ __host__ __forceinline__ int gdec(int g) {
    int p = g;
    p ^= p >> 1; p ^= p >> 2; p ^= p >> 4; p ^= p >> 8; p ^= p >> 16;
    return p;
}
__device__ __forceinline__ int gd6(int u) {
    int p = u; p ^= p >> 1; p ^= p >> 2; p ^= p >> 4; return p & 63;
}

// ---------------------------------------------------------------------------
// HH kernel: (R5_l1) * H1 * P * (H0 x R5_l0). Orbit = g bits 19:14
// in registers; pos bit 13 lives on lane bit 0 so conj(R5_l1) is warp-local.
//   pos = (t0<<13) | (sub<<7) | (w<<4) | t[4:1]
// ---------------------------------------------------------------------------
__global__ void __launch_bounds__(256, 2) hh_kernel(const float* __restrict__ in,
                                                    float* __restrict__ out) {
    cudaGridDependencySynchronize();       // PDL: wait before reading any global
    const int blk = blockIdx.x;                   // CB*64
    const int tid = threadIdx.x;
    const int t0  = tid & 1;
    const int w   = tid >> 5;                     // 0..7
    const int tl  = (tid >> 1) & 15;              // pos bits 3:0
    const int sub = blk & 63;
    const int pos = (t0 << 13) | (sub << 7) | (w << 4) | tl;
    const size_t bbase = (size_t)(blk >> 6) << 20;

    float e[64];
    const float* pin = in + bbase + pos;
#pragma unroll
    for (int u = 0; u < 64; u++) e[u] = pin[u << 14];

    const float2* rf0 = g_rf;           // layer 0
    const float2* rf1 = g_rf + NQ;      // layer 1

    // layer-0 high stages (g-domain, plain): qubit q at u bit (5-q)
    stage_fg<64>(e, 32, rf0[0]);
    stage_fg<64>(e, 16, rf0[1]);
    stage_fg<64>(e,  8, rf0[2]);
    stage_fg<64>(e,  4, rf0[3]);
    stage_fg<64>(e,  2, rf0[4]);
    stage_fg<64>(e,  1, rf0[5]);

    // conj(H1): qubit q -> HB = 5-q
    conj_stage<5>(e, rf1[0]);
    conj_stage<4>(e, rf1[1]);
    conj_stage<3>(e, rf1[2]);
    conj_stage<2>(e, rf1[3]);
    conj_stage<1>(e, rf1[4]);
    conj_r5_stage(e, rf1[5]);

    // scatter with P
    const int A = gdec(pos);
    float* pa = out + bbase + A;
    float* pb = out + bbase + (A ^ 0x3FFF);
#pragma unroll
    for (int u = 0; u < 64; u++) {
        int hi = gd6(u) << 14;
        if (__popc(u) & 1) pb[hi] = e[u];
        else               pa[hi] = e[u];
    }
}

// ---------------------------------------------------------------------------
// PH kernel: (H_l x R5_l) * P over qubits 0..5 (64-element orbit).
// Gather at g = genc(k<<14 | pos) = ((k<<14)^(k<<13)) ^ (pos^(pos>>1)).
// ---------------------------------------------------------------------------
__global__ void __launch_bounds__(256, 2) ph_kernel(const float* __restrict__ in,
                                                    float* __restrict__ out,
                                                    int layer) {
    cudaGridDependencySynchronize();       // PDL
    const int blk = blockIdx.x;                   // CB*64
    const int pos = (blk & 63) * 256 + threadIdx.x;   // 14-bit position
    const size_t bbase = (size_t)(blk >> 6) << 20;
    const int G = pos ^ (pos >> 1);

    float e[64];
    const float* pin = in + bbase;
#pragma unroll
    for (int k = 0; k < 64; k++)
        e[k] = pin[((k << 14) ^ (k << 13)) ^ G];

    const float2* rf = g_rf + layer * NQ;
    stage_fg<64>(e, 32, rf[0]);
    stage_fg<64>(e, 16, rf[1]);
    stage_fg<64>(e,  8, rf[2]);
    stage_fg<64>(e,  4, rf[3]);
    stage_fg<64>(e,  2, rf[4]);
    stage_fg<64>(e,  1, rf[5]);

    float* pout = out + bbase + pos;
#pragma unroll
    for (int k = 0; k < 64; k++) pout[k << 14] = e[k];
}

// ---------------------------------------------------------------------------
// LOW14 kernel: qubits 6..19 inside contiguous 16384-float tiles.
// 512 threads x 32 regs, 64 KB smem -> 2 CTAs/SM.
// idx = j*512 + w*32 + t (j: bits 13:9, w: 8:5, t: 4:0); idx bit b <-> qubit 19-b.
// Phase1: shuffles q19..15; reg stages q6..10. Transpose swaps j[3:0] <-> w.
// Phase2: reg stages q11..14. FINAL folds last P + abs*|C| into scatter.
// ---------------------------------------------------------------------------
template <bool FINAL>
__global__ void __launch_bounds__(512, 2) low14_kernel(const float* in,
                                                       float* out,
                                                       int layer) {
    cudaGridDependencySynchronize();       // PDL
    extern __shared__ float sm[];          // 16384 floats = 64 KB
    const int t = threadIdx.x & 31;
    const int w = threadIdx.x >> 5;        // 0..15
    const int blk = blockIdx.x;            // CB*64
    const int tile = blk & 63;
    const size_t bbase = (size_t)(blk >> 6) << 20;
    const size_t tbase = bbase + ((size_t)tile << 14);

    float e[32];
    const float* p = in + tbase;
#pragma unroll
    for (int j = 0; j < 32; j++) e[j] = p[j * 512 + w * 32 + t];

    const float2* rf = g_rf + layer * NQ;
    stage_xlane_fg(e, 0, rf[19], t);
    stage_xlane_fg(e, 1, rf[18], t);
    stage_xlane_fg(e, 2, rf[17], t);
    stage_xlane_fg(e, 3, rf[16], t);
    stage_xlane_fg(e, 4, rf[15], t);
    stage_fg<32>(e, 16, rf[6]);
    stage_fg<32>(e,  8, rf[7]);
    stage_fg<32>(e,  4, rf[8]);
    stage_fg<32>(e,  2, rf[9]);
    stage_fg<32>(e,  1, rf[10]);

#pragma unroll
    for (int j = 0; j < 32; j++) sm[j * 512 + w * 32 + t] = e[j];
    __syncthreads();
#pragma unroll
    for (int j = 0; j < 32; j++)
        e[j] = sm[(j >> 4) * 8192 + w * 512 + (j & 15) * 32 + t];

    // now e[j]: idx = ((j>>4)<<13) | (w<<9) | ((j&15)<<5) | t
    stage_fg<32>(e, 8, rf[11]);
    stage_fg<32>(e, 4, rf[12]);
    stage_fg<32>(e, 2, rf[13]);
    stage_fg<32>(e, 1, rf[14]);

    if (FINAL) {
        const int   pbase = gdec((tile << 14) | (w << 9) | t);
        const float absC  = g_absC;
#pragma unroll
        for (int j = 0; j < 32; j++) {
            int cj = gdec(((j >> 4) << 13) | ((j & 15) << 5));  // folds to const
            out[bbase + (pbase ^ cj)] = fabsf(e[j]) * absC;
        }
    } else {
        float* q = out + tbase;
#pragma unroll
        for (int j = 0; j < 32; j++)
            q[(j >> 4) * 8192 + w * 512 + (j & 15) * 32 + t] = e[j];
    }
}

// ---------------------------------------------------------------------------
// Host side: every launch carries the PDL (programmatic stream serialization)
// attribute so kernel k+1's blocks dispatch while kernel k drains; the
// cudaGridDependencySynchronize() at each kernel's top restores ordering.
// ---------------------------------------------------------------------------
static cudaLaunchAttribute g_pdl_attr[1];

static inline cudaLaunchConfig_t mkcfg(unsigned grid, unsigned block, size_t smem) {
    cudaLaunchConfig_t c{};
    c.gridDim  = dim3(grid, 1, 1);
    c.blockDim = dim3(block, 1, 1);
    c.dynamicSmemBytes = smem;
    c.stream = 0;
    g_pdl_attr[0].id = cudaLaunchAttributeProgrammaticStreamSerialization;
    g_pdl_attr[0].val.programmaticStreamSerializationAllowed = 1;
    c.attrs = g_pdl_attr;
    c.numAttrs = 1;
    return c;
}

extern "C" void kernel_launch(void* const* d_in, const int* in_sizes, int n_in,
                              void* d_out, int out_size) {
    const float* x     = (const float*)d_in[0];
    const float* theta = (const float*)d_in[1];
    float*       out   = (float*)d_out;

    float *bA = nullptr, *bB = nullptr;
    cudaGetSymbolAddress((void**)&bA, g_bufA);
    cudaGetSymbolAddress((void**)&bB, g_bufB);

    const int SM14 = 16384 * sizeof(float);
    cudaFuncSetAttribute(low14_kernel<false>, cudaFuncAttributeMaxDynamicSharedMemorySize, SM14);
    cudaFuncSetAttribute(low14_kernel<true>,  cudaFuncAttributeMaxDynamicSharedMemorySize, SM14);

    sincos_kernel<<<1, 128>>>(theta);

    const int GH = CB * 64;   // all grids

    cudaLaunchConfig_t cL = mkcfg(GH, 512, SM14);  // low14
    cudaLaunchConfig_t cH = mkcfg(GH, 256, 0);     // hh / ph

    for (int c = 0; c < NCHUNK; c++) {
        const float* xc = x   + ((size_t)c * CB << 20);
        float*       oc = out + ((size_t)c * CB << 20);

        cudaLaunchKernelEx(&cL, low14_kernel<false>, xc, bA, 0);   // L0 (q6..19)
        cudaLaunchKernelEx(&cH, hh_kernel, (const float*)bA, bB);  // R5l1*H1*P*(H0,R5l0)
        cudaLaunchKernelEx(&cL, low14_kernel<false>, (const float*)bB, bB, 1); // L1
        cudaLaunchKernelEx(&cH, ph_kernel, (const float*)bB, bA, 2);           // (H2,R5l2)*P
        cudaLaunchKernelEx(&cL, low14_kernel<false>, (const float*)bA, bA, 2); // L2
        cudaLaunchKernelEx(&cH, ph_kernel, (const float*)bA, bB, 3);           // (H3,R5l3)*P
        cudaLaunchKernelEx(&cL, low14_kernel<true>,  (const float*)bB, oc, 3); // P*L3
    }
}

// round 13
// speedup vs baseline: 1.2022x; 1.0565x over previous
#include <cuda_runtime.h>
#include <math.h>
#include <stdint.h>

#define NQ    20
#define NL    4
#define BATCH 16
#define DIM   (1 << NQ)

__device__ float  g_bufA[BATCH * DIM];   // 64 MB
__device__ float  g_bufB[BATCH * DIM];   // 64 MB
__device__ float2 g_rf[NL * NQ];   // .x = ratio (|r|<=1), .y = form (0 or 1)
__device__ float  g_absC;          // |product of per-gate scales|

// ---------------------------------------------------------------------------
// Fast-Givens precompute.
//   form0 (|c|>=|s|): M = c*[[1,-t],[t,1]], t=s/c
//   form1 (|s|> |c|): M = s*[[u,-1],[1,u]], u=c/s
// ---------------------------------------------------------------------------
__global__ void sincos_kernel(const float* __restrict__ theta) {
    __shared__ float sc[NL * NQ];
    int i = threadIdx.x;
    if (i < NL * NQ) {
        float t = 0.5f * theta[i];
        float c = cosf(t), s = sinf(t);
        bool form = fabsf(s) > fabsf(c);
        g_rf[i] = make_float2(form ? (c / s) : (s / c), form ? 1.0f : 0.0f);
        sc[i] = form ? s : c;
    }
    __syncthreads();
    if (i == 0) {
        float p = 1.0f;
        for (int k = 0; k < NL * NQ; k++) p *= sc[k];
        g_absC = fabsf(p);
    }
}

// ---------------------------------------------------------------------------
// Fast-Givens butterflies. 'a' = role-0 element:
//   form0: a' = a - r*b ; b' = b + r*a
//   form1: a' = r*a - b ; b' = r*b + a
// ---------------------------------------------------------------------------
template <int N>
__device__ __forceinline__ void stage_fg(float* e, int m, float2 rf) {
    float r = rf.x;
    if (rf.y == 0.0f) {
#pragma unroll
        for (int j = 0; j < N; j++)
            if ((j & m) == 0) {
                float a = e[j], b = e[j | m];
                e[j]     = fmaf(-r, b, a);
                e[j | m] = fmaf( r, a, b);
            }
    } else {
#pragma unroll
        for (int j = 0; j < N; j++)
            if ((j & m) == 0) {
                float a = e[j], b = e[j | m];
                e[j]     = fmaf(r, a, -b);
                e[j | m] = fmaf(r, b,  a);
            }
    }
}

__device__ __forceinline__ float xsign(float v, uint32_t sg) {
    return __uint_as_float(__float_as_uint(v) ^ sg);
}

__device__ __forceinline__ void stage_xlane_fg(float e[32], int kbit, float2 rf, int lane) {
    int bit = (lane >> kbit) & 1;
    if (rf.y == 0.0f) {
        float rs = bit ? rf.x : -rf.x;
#pragma unroll
        for (int j = 0; j < 32; j++) {
            float o = __shfl_xor_sync(0xffffffffu, e[j], 1 << kbit);
            e[j] = fmaf(rs, o, e[j]);
        }
    } else {
        float r = rf.x;
        uint32_t sg = bit ? 0u : 0x80000000u;
#pragma unroll
        for (int j = 0; j < 32; j++) {
            float o = __shfl_xor_sync(0xffffffffu, e[j], 1 << kbit);
            e[j] = fmaf(r, e[j], xsign(o, sg));
        }
    }
}

// Conjugated H stage (P^-1 H P): couples u-pairs differing in bits {hb, hb-1};
// role(u) = parity(u >> hb).
template <int HB>
__device__ __forceinline__ void conj_stage(float e[64], float2 rf) {
    const int mask = 3 << (HB - 1);
    float r = rf.x;
    bool f1 = (rf.y != 0.0f);
    if (!f1) {
#pragma unroll
        for (int u = 0; u < 64; u++)
            if ((u & (1 << HB)) == 0) {
                int v = u ^ mask;
                int ra = __popc(u >> HB) & 1;
                int ia = ra ? v : u;
                int ib = ra ? u : v;
                float a = e[ia], b = e[ib];
                e[ia] = fmaf(-r, b, a);
                e[ib] = fmaf( r, a, b);
            }
    } else {
#pragma unroll
        for (int u = 0; u < 64; u++)
            if ((u & (1 << HB)) == 0) {
                int v = u ^ mask;
                int ra = __popc(u >> HB) & 1;
                int ia = ra ? v : u;
                int ib = ra ? u : v;
                float a = e[ia], b = e[ib];
                e[ia] = fmaf(r, a, -b);
                e[ib] = fmaf(r, b,  a);
            }
    }
}

// Conjugated R5(layer1) stage inside hh: couples g bits {14,13} = (reg bit 0,
// lane bit 0). Partner of e[u] is shfl_xor(e[u^1], 1). Role 'a' = parity(u)==0.
__device__ __forceinline__ void conj_r5_stage(float e[64], float2 rf) {
    float r = rf.x;
    bool f1 = (rf.y != 0.0f);
#pragma unroll
    for (int u = 0; u < 64; u += 2) {
        float o0 = __shfl_xor_sync(0xffffffffu, e[u + 1], 1);
        float o1 = __shfl_xor_sync(0xffffffffu, e[u],     1);
        bool aFirst = ((__popc(u) & 1) == 0);
        if (!f1) {
            if (aFirst) {
                e[u]     = fmaf(-r, o0, e[u]);
                e[u + 1] = fmaf( r, o1, e[u + 1]);
            } else {
                e[u]     = fmaf( r, o0, e[u]);
                e[u + 1] = fmaf(-r, o1, e[u + 1]);
            }
        } else {
            if (aFirst) {
                e[u]     = fmaf(r, e[u],     -o0);
                e[u + 1] = fmaf(r, e[u + 1],  o1);
            } else {
                e[u]     = fmaf(r, e[u],      o0);
                e[u + 1] = fmaf(r, e[u + 1], -o1);
            }
        }
    }
}

// gray decode (p such that p ^ (p>>1) = g)
__device__ __host__ __forceinline__ int gdec(int g) {
    int p = g;
    p ^= p >> 1; p ^= p >> 2; p ^= p >> 4; p ^= p >> 8; p ^= p >> 16;
    return p;
}
__device__ __forceinline__ int gd6(int u) {
    int p = u; p ^= p >> 1; p ^= p >> 2; p ^= p >> 4; return p & 63;
}

// ---------------------------------------------------------------------------
// HH kernel: (R5_l1) * H1 * P * (H0 x R5_l0). Orbit = g bits 19:14
// in registers; pos bit 13 lives on lane bit 0 so conj(R5_l1) is warp-local.
//   pos = (t0<<13) | (sub<<7) | (w<<4) | t[4:1]      grid = 16*64
// ---------------------------------------------------------------------------
__global__ void __launch_bounds__(256, 2) hh_kernel(const float* __restrict__ in,
                                                    float* __restrict__ out) {
    cudaGridDependencySynchronize();       // PDL: wait before reading any global
    const int blk = blockIdx.x;                   // BATCH*64
    const int tid = threadIdx.x;
    const int t0  = tid & 1;
    const int w   = tid >> 5;                     // 0..7
    const int tl  = (tid >> 1) & 15;              // pos bits 3:0
    const int sub = blk & 63;
    const int pos = (t0 << 13) | (sub << 7) | (w << 4) | tl;
    const size_t bbase = (size_t)(blk >> 6) << 20;

    float e[64];
    const float* pin = in + bbase + pos;
#pragma unroll
    for (int u = 0; u < 64; u++) e[u] = pin[u << 14];

    const float2* rf0 = g_rf;           // layer 0
    const float2* rf1 = g_rf + NQ;      // layer 1

    // layer-0 high stages (g-domain, plain): qubit q at u bit (5-q)
    stage_fg<64>(e, 32, rf0[0]);
    stage_fg<64>(e, 16, rf0[1]);
    stage_fg<64>(e,  8, rf0[2]);
    stage_fg<64>(e,  4, rf0[3]);
    stage_fg<64>(e,  2, rf0[4]);
    stage_fg<64>(e,  1, rf0[5]);

    // conj(H1): qubit q -> HB = 5-q
    conj_stage<5>(e, rf1[0]);
    conj_stage<4>(e, rf1[1]);
    conj_stage<3>(e, rf1[2]);
    conj_stage<2>(e, rf1[3]);
    conj_stage<1>(e, rf1[4]);
    conj_r5_stage(e, rf1[5]);

    // scatter with P
    const int A = gdec(pos);
    float* pa = out + bbase + A;
    float* pb = out + bbase + (A ^ 0x3FFF);
#pragma unroll
    for (int u = 0; u < 64; u++) {
        int hi = gd6(u) << 14;
        if (__popc(u) & 1) pb[hi] = e[u];
        else               pa[hi] = e[u];
    }
}

// ---------------------------------------------------------------------------
// PH kernel: (H_l x R5_l) * P over qubits 0..5 (64-element orbit).
// Gather at g = genc(k<<14 | pos) = ((k<<14)^(k<<13)) ^ (pos^(pos>>1)).
// grid = 16*64, 256 threads.
// ---------------------------------------------------------------------------
__global__ void __launch_bounds__(256, 2) ph_kernel(const float* __restrict__ in,
                                                    float* __restrict__ out,
                                                    int layer) {
    cudaGridDependencySynchronize();       // PDL
    const int blk = blockIdx.x;                   // BATCH*64
    const int pos = (blk & 63) * 256 + threadIdx.x;   // 14-bit position
    const size_t bbase = (size_t)(blk >> 6) << 20;
    const int G = pos ^ (pos >> 1);

    float e[64];
    const float* pin = in + bbase;
#pragma unroll
    for (int k = 0; k < 64; k++)
        e[k] = pin[((k << 14) ^ (k << 13)) ^ G];

    const float2* rf = g_rf + layer * NQ;
    stage_fg<64>(e, 32, rf[0]);
    stage_fg<64>(e, 16, rf[1]);
    stage_fg<64>(e,  8, rf[2]);
    stage_fg<64>(e,  4, rf[3]);
    stage_fg<64>(e,  2, rf[4]);
    stage_fg<64>(e,  1, rf[5]);

    float* pout = out + bbase + pos;
#pragma unroll
    for (int k = 0; k < 64; k++) pout[k << 14] = e[k];
}

// ---------------------------------------------------------------------------
// LOW14 kernel: qubits 6..19 inside contiguous 16384-float tiles.
// 512 threads x 32 regs, 64 KB smem -> 2 CTAs/SM. grid = 16*64.
// idx = j*512 + w*32 + t (j: bits 13:9, w: 8:5, t: 4:0); idx bit b <-> qubit 19-b.
// Phase1: shuffles q19..15; reg stages q6..10. Transpose swaps j[3:0] <-> w.
// Phase2: reg stages q11..14. FINAL folds last P + abs*|C| into scatter.
// ---------------------------------------------------------------------------
template <bool FINAL>
__global__ void __launch_bounds__(512, 2) low14_kernel(const float* in,
                                                       float* out,
                                                       int layer) {
    cudaGridDependencySynchronize();       // PDL
    extern __shared__ float sm[];          // 16384 floats = 64 KB
    const int t = threadIdx.x & 31;
    const int w = threadIdx.x >> 5;        // 0..15
    const int blk = blockIdx.x;            // BATCH*64
    const int tile = blk & 63;
    const size_t bbase = (size_t)(blk >> 6) << 20;
    const size_t tbase = bbase + ((size_t)tile << 14);

    float e[32];
    const float* p = in + tbase;
#pragma unroll
    for (int j = 0; j < 32; j++) e[j] = p[j * 512 + w * 32 + t];

    const float2* rf = g_rf + layer * NQ;
    stage_xlane_fg(e, 0, rf[19], t);
    stage_xlane_fg(e, 1, rf[18], t);
    stage_xlane_fg(e, 2, rf[17], t);
    stage_xlane_fg(e, 3, rf[16], t);
    stage_xlane_fg(e, 4, rf[15], t);
    stage_fg<32>(e, 16, rf[6]);
    stage_fg<32>(e,  8, rf[7]);
    stage_fg<32>(e,  4, rf[8]);
    stage_fg<32>(e,  2, rf[9]);
    stage_fg<32>(e,  1, rf[10]);

#pragma unroll
    for (int j = 0; j < 32; j++) sm[j * 512 + w * 32 + t] = e[j];
    __syncthreads();
#pragma unroll
    for (int j = 0; j < 32; j++)
        e[j] = sm[(j >> 4) * 8192 + w * 512 + (j & 15) * 32 + t];

    // now e[j]: idx = ((j>>4)<<13) | (w<<9) | ((j&15)<<5) | t
    stage_fg<32>(e, 8, rf[11]);
    stage_fg<32>(e, 4, rf[12]);
    stage_fg<32>(e, 2, rf[13]);
    stage_fg<32>(e, 1, rf[14]);

    if (FINAL) {
        const int   pbase = gdec((tile << 14) | (w << 9) | t);
        const float absC  = g_absC;
#pragma unroll
        for (int j = 0; j < 32; j++) {
            int cj = gdec(((j >> 4) << 13) | ((j & 15) << 5));  // folds to const
            out[bbase + (pbase ^ cj)] = fabsf(e[j]) * absC;
        }
    } else {
        float* q = out + tbase;
#pragma unroll
        for (int j = 0; j < 32; j++)
            q[(j >> 4) * 8192 + w * 512 + (j & 15) * 32 + t] = e[j];
    }
}

// ---------------------------------------------------------------------------
// Host: single de-chunked pipeline (8 launches), PDL on every boundary.
// ---------------------------------------------------------------------------
static cudaLaunchAttribute g_pdl_attr[1];

static inline cudaLaunchConfig_t mkcfg(unsigned grid, unsigned block, size_t smem) {
    cudaLaunchConfig_t c{};
    c.gridDim  = dim3(grid, 1, 1);
    c.blockDim = dim3(block, 1, 1);
    c.dynamicSmemBytes = smem;
    c.stream = 0;
    g_pdl_attr[0].id = cudaLaunchAttributeProgrammaticStreamSerialization;
    g_pdl_attr[0].val.programmaticStreamSerializationAllowed = 1;
    c.attrs = g_pdl_attr;
    c.numAttrs = 1;
    return c;
}

extern "C" void kernel_launch(void* const* d_in, const int* in_sizes, int n_in,
                              void* d_out, int out_size) {
    const float* x     = (const float*)d_in[0];
    const float* theta = (const float*)d_in[1];
    float*       out   = (float*)d_out;

    float *bA = nullptr, *bB = nullptr;
    cudaGetSymbolAddress((void**)&bA, g_bufA);
    cudaGetSymbolAddress((void**)&bB, g_bufB);

    const int SM14 = 16384 * sizeof(float);
    cudaFuncSetAttribute(low14_kernel<false>, cudaFuncAttributeMaxDynamicSharedMemorySize, SM14);
    cudaFuncSetAttribute(low14_kernel<true>,  cudaFuncAttributeMaxDynamicSharedMemorySize, SM14);

    sincos_kernel<<<1, 128>>>(theta);

    const int G = BATCH * 64;   // 1024 blocks for every pass

    cudaLaunchConfig_t cL = mkcfg(G, 512, SM14);  // low14
    cudaLaunchConfig_t cH = mkcfg(G, 256, 0);     // hh / ph

    cudaLaunchKernelEx(&cL, low14_kernel<false>, x, bA, 0);                // L0
    cudaLaunchKernelEx(&cH, hh_kernel, (const float*)bA, bB);              // H1*P*H0'
    cudaLaunchKernelEx(&cL, low14_kernel<false>, (const float*)bB, bB, 1); // L1 (in-place)
    cudaLaunchKernelEx(&cH, ph_kernel, (const float*)bB, bA, 2);           // (H2,R5l2)*P
    cudaLaunchKernelEx(&cL, low14_kernel<false>, (const float*)bA, bA, 2); // L2 (in-place)
    cudaLaunchKernelEx(&cH, ph_kernel, (const float*)bA, bB, 3);           // (H3,R5l3)*P
    cudaLaunchKernelEx(&cL, low14_kernel<true>,  (const float*)bB, out, 3); // P*L3, abs*|C|
}